// round 17
// baseline (speedup 1.0000x reference)
#include <cuda_runtime.h>
#include <cuda_fp16.h>

#define D 4096
#define NSTEPS 50
#define NCTA 147
#define ROWS_PER_CTA 28
#define CACHED_ROWS 12           // rows per CTA held in SMEM (192 KB)
#define NTHREADS 1024
#define NBAR 8                   // barrier counter shards (distinct L2 lines)

// Interleaved fp16 matrices: g_AB[r*2D + 2j] = A[r][j] (lo), [..+1] = B[r][j] (hi).
__device__ __align__(16) __half g_AB[(size_t)2 * D * D];
// Packed (theta_t, delta_t) half2 per element, published by the row owner.
__device__ __align__(16) unsigned int g_td[D];
// Sharded arrival counters, 128B stride -> 8 distinct L2 lines.
__device__ unsigned int g_bar[NBAR * 32];

// ---------------------------------------------------------------------------
// prep: interleave A,B into fp16 pairs; reset the barrier shards.
// ---------------------------------------------------------------------------
__global__ void __launch_bounds__(256) prep_kernel(const float* __restrict__ A,
                                                   const float* __restrict__ B) {
    if (blockIdx.x == 0 && threadIdx.x < NBAR * 32) g_bar[threadIdx.x] = 0;
    size_t i = (size_t)blockIdx.x * blockDim.x + threadIdx.x;  // float4 index
    float4 a = ((const float4*)A)[i];
    float4 b = ((const float4*)B)[i];
    uint4 o;
    __half2 p;
    p = __floats2half2_rn(a.x, b.x); o.x = *(unsigned int*)&p;   // lo=A, hi=B
    p = __floats2half2_rn(a.y, b.y); o.y = *(unsigned int*)&p;
    p = __floats2half2_rn(a.z, b.z); o.z = *(unsigned int*)&p;
    p = __floats2half2_rn(a.w, b.w); o.w = *(unsigned int*)&p;
    ((uint4*)g_AB)[i] = o;
}

// acc += Sum over 8 elements of (A_j*t_j + B_j*d_j): two uint4 pairs
// accumulated in one fp16 chain (8 HFMA2), then a single fp32 fold.
__device__ __forceinline__ float dotAB8(uint4 m0, uint4 v0,
                                        uint4 m1, uint4 v1, float acc) {
    __half2 p = __hmul2(*(__half2*)&m0.x, *(__half2*)&v0.x);
    p = __hfma2(*(__half2*)&m0.y, *(__half2*)&v0.y, p);
    p = __hfma2(*(__half2*)&m0.z, *(__half2*)&v0.z, p);
    p = __hfma2(*(__half2*)&m0.w, *(__half2*)&v0.w, p);
    p = __hfma2(*(__half2*)&m1.x, *(__half2*)&v1.x, p);
    p = __hfma2(*(__half2*)&m1.y, *(__half2*)&v1.y, p);
    p = __hfma2(*(__half2*)&m1.z, *(__half2*)&v1.z, p);
    p = __hfma2(*(__half2*)&m1.w, *(__half2*)&v1.w, p);
    float2 f = __half22float2(p);
    return acc + f.x + f.y;
}

// ---------------------------------------------------------------------------
// Persistent recurrence kernel: 147 CTAs x 1024 threads, 28 rows/CTA.
// Same structure as the 307us kernel; the inner loop now folds fp16 partials
// every 8 elements (two uint4 pairs per fold) -> ~21% fewer fma-pipe ops.
// Staging: single LDG.128 + STS.128 per thread from g_td (owners pre-pack).
// Sharded-counter barrier; 3 block syncs per step.
// SMEM: s_td 16K | part 512B | cached rows 192K = 208.5 KB.
// ---------------------------------------------------------------------------
__global__ void __launch_bounds__(NTHREADS, 1) rnn_kernel(const float* __restrict__ init,
                                                          float* __restrict__ out) {
    extern __shared__ char smem[];
    uint4*  s_td   = (uint4*)smem;                     // (t,d) half2    (16 KB)
    float*  s_part = (float*)(smem + 16384);           // partials       (512 B)
    uint4*  s_mat  = (uint4*)(smem + 16896);           // cached rows    (192 KB)

    const int tid  = threadIdx.x;
    const int warp = tid >> 5;
    const int lane = tid & 31;
    const int rg   = warp >> 2;                        // 0..7 (7 idle)
    const int ks   = warp & 3;                         // 0..3
    const int row_base = blockIdx.x * ROWS_PER_CTA;
    const int row0 = row_base + rg * 4;
    const bool rowOK  = (rg < 7) && (row0 < D);
    const bool cached = (rg < CACHED_ROWS / 4);        // rg 0..2 -> SMEM rows
    const int seg = ks * 256;                          // uint4 offset of segment

    // Preload cached rows into SMEM (once).  Clamp OOB rows of the last CTA.
#pragma unroll
    for (int it = 0; it < CACHED_ROWS; ++it) {
        int sr = min(row_base + it, D - 1);
        s_mat[it * 1024 + tid] = ((const uint4*)g_AB)[(size_t)sr * 1024 + tid];
    }

    // Streamed-row pointers (rg >= 3), clamped for the partially-OOB last CTA
    const uint4* r0 = (const uint4*)g_AB + (size_t)min(row0 + 0, D - 1) * 1024;
    const uint4* r1 = (const uint4*)g_AB + (size_t)min(row0 + 1, D - 1) * 1024;
    const uint4* r2 = (const uint4*)g_AB + (size_t)min(row0 + 2, D - 1) * 1024;
    const uint4* r3 = (const uint4*)g_AB + (size_t)min(row0 + 3, D - 1) * 1024;
    // Cached-row pointers (rg < 3)
    const uint4* c0 = s_mat + (size_t)(rg * 4 + 0) * 1024;
    const uint4* c1 = s_mat + (size_t)(rg * 4 + 1) * 1024;
    const uint4* c2 = s_mat + (size_t)(rg * 4 + 2) * 1024;
    const uint4* c3 = s_mat + (size_t)(rg * 4 + 3) * 1024;

    // Writer state: this thread owns row (row_base + tid) if tid < 28.
    const int wrow = row_base + tid;
    const bool writer = (tid < ROWS_PER_CTA) && (wrow < D);
    float th_prev = writer ? init[D + wrow] : 0.f;     // theta_0[row]

    // ---- Stage step 0 from init: theta_0 = init[D..2D), theta_{-1} = init[0..D)
    {
        float4 nt = ((const float4*)(init + D))[tid];
        float4 pt = ((const float4*)init)[tid];
        uint4 v;
        __half2 h;
        h = __floats2half2_rn(nt.x, nt.x - pt.x); v.x = *(unsigned int*)&h;
        h = __floats2half2_rn(nt.y, nt.y - pt.y); v.y = *(unsigned int*)&h;
        h = __floats2half2_rn(nt.z, nt.z - pt.z); v.z = *(unsigned int*)&h;
        h = __floats2half2_rn(nt.w, nt.w - pt.w); v.w = *(unsigned int*)&h;
        s_td[tid] = v;
    }
    __syncthreads();

    for (int t = 0; t < NSTEPS; ++t) {
        if (t > 0) {
            s_td[tid] = __ldcg((const uint4*)g_td + tid);   // pre-packed by owners
            __syncthreads();
        }

        if (rowOK) {
            float a0 = 0.f, a1 = 0.f, a2 = 0.f, a3 = 0.f;
            if (cached) {
#pragma unroll 2
                for (int i = 0; i < 4; ++i) {
                    int idx0 = seg + i * 64 + lane;
                    int idx1 = idx0 + 32;
                    uint4 v0 = s_td[idx0];
                    uint4 v1 = s_td[idx1];
                    a0 = dotAB8(c0[idx0], v0, c0[idx1], v1, a0);
                    a1 = dotAB8(c1[idx0], v0, c1[idx1], v1, a1);
                    a2 = dotAB8(c2[idx0], v0, c2[idx1], v1, a2);
                    a3 = dotAB8(c3[idx0], v0, c3[idx1], v1, a3);
                }
            } else {
#pragma unroll 2
                for (int i = 0; i < 4; ++i) {
                    int idx0 = seg + i * 64 + lane;
                    int idx1 = idx0 + 32;
                    uint4 v0 = s_td[idx0];
                    uint4 v1 = s_td[idx1];
                    a0 = dotAB8(r0[idx0], v0, r0[idx1], v1, a0);
                    a1 = dotAB8(r1[idx0], v0, r1[idx1], v1, a1);
                    a2 = dotAB8(r2[idx0], v0, r2[idx1], v1, a2);
                    a3 = dotAB8(r3[idx0], v0, r3[idx1], v1, a3);
                }
            }
#pragma unroll
            for (int off = 16; off; off >>= 1) {
                a0 += __shfl_xor_sync(0xffffffffu, a0, off);
                a1 += __shfl_xor_sync(0xffffffffu, a1, off);
                a2 += __shfl_xor_sync(0xffffffffu, a2, off);
                a3 += __shfl_xor_sync(0xffffffffu, a3, off);
            }
            if (lane == 0) {
                s_part[(rg * 4 + 0) * 4 + ks] = a0;
                s_part[(rg * 4 + 1) * 4 + ks] = a1;
                s_part[(rg * 4 + 2) * 4 + ks] = a2;
                s_part[(rg * 4 + 3) * 4 + ks] = a3;
            }
        }
        __syncthreads();                               // partials ready

        // ---- Warp 0: combine, publish fp32 + packed fp16, run barrier ----
        if (warp == 0) {
            if (writer) {
                float v = (s_part[tid * 4 + 0] + s_part[tid * 4 + 1]) +
                          (s_part[tid * 4 + 2] + s_part[tid * 4 + 3]);
                __stcg(out + (size_t)t * D + wrow, v);
                float dlt = v - th_prev;               // exact fp32, from register
                th_prev = v;
                __half2 h = __floats2half2_rn(v, dlt);
                __stcg(&g_td[wrow], *(unsigned int*)&h);
            }
            __syncwarp();
            if (lane == 0) {
                __threadfence();                       // release rows + g_td
                atomicAdd(&g_bar[(blockIdx.x & (NBAR - 1)) * 32], 1u);
                const unsigned int target = (unsigned int)(t + 1) * NCTA;
                unsigned int sum;
                do {
                    sum = 0;
#pragma unroll
                    for (int k = 0; k < NBAR; ++k)
                        sum += *(volatile unsigned int*)&g_bar[k * 32];
                } while (sum < target);
                __threadfence();                       // acquire
            }
            __syncwarp();
        }
        __syncthreads();                               // release all warps
    }
}

// ---------------------------------------------------------------------------
// Launch: prep (convert + barrier reset), then ONE persistent kernel with
// opt-in 208.5 KB dynamic SMEM (1 CTA/SM, 147 co-resident).
// ---------------------------------------------------------------------------
extern "C" void kernel_launch(void* const* d_in, const int* in_sizes, int n_in,
                              void* d_out, int out_size) {
    const float* init = (const float*)d_in[0];  // [2, D]
    const float* A    = (const float*)d_in[1];  // [D, D]
    const float* B    = (const float*)d_in[2];  // [D, D]
    float* out = (float*)d_out;                 // [NSTEPS, D]

    const int smem_bytes = 16896 + CACHED_ROWS * 1024 * 16;  // 213,504 B
    cudaFuncSetAttribute(rnn_kernel, cudaFuncAttributeMaxDynamicSharedMemorySize,
                         smem_bytes);

    prep_kernel<<<(D * (size_t)D / 4) / 256, 256>>>(A, B);
    rnn_kernel<<<NCTA, NTHREADS, smem_bytes>>>(init, out);
}